// round 2
// baseline (speedup 1.0000x reference)
#include <cuda_runtime.h>
#include <math.h>

#define KK   8
#define H    250
#define HP   252          // padded row stride (float4-aligned)
#define NP   56           // K*(K-1) pairs per group
#define HA_  100
#define MM   576
#define NB   2048         // batch groups
#define BK   (NB*KK)
#define CIN  1076         // 250 + 250 + 576
#define EPS_ 1e-5f

// scratch (allocation-free rule: device globals)
__device__ float g_s1[(size_t)BK * H];
__device__ float g_eff[(size_t)BK * H];

// ---------------------------------------------------------------------------
// Kernel 1: s1 = LN(relu(state @ enc_W + enc_b)); one block per group (8 rows)
// ---------------------------------------------------------------------------
__global__ __launch_bounds__(256, 2) void enc_kernel(
    const float* __restrict__ state, const float* __restrict__ W,
    const float* __restrict__ b, const float* __restrict__ g,
    const float* __restrict__ bt)
{
    __shared__ float sst[KK * HP];
    __shared__ float hbuf[KK * HP];
    __shared__ float st[KK * 2];

    const int t = threadIdx.x;
    const int grp = blockIdx.x;
    const float* srow = state + (size_t)grp * KK * H;

    for (int i = t; i < KK * H; i += 256) {
        int r = i / H, c = i % H;
        sst[r * HP + c] = srow[i];
    }
    __syncthreads();

    float acc[KK];
    if (t < H) {
        #pragma unroll
        for (int e = 0; e < KK; e++) acc[e] = 0.f;
        #pragma unroll 1
        for (int k = 0; k < 248; k += 4) {
            float w0 = W[(k + 0) * H + t];
            float w1 = W[(k + 1) * H + t];
            float w2 = W[(k + 2) * H + t];
            float w3 = W[(k + 3) * H + t];
            #pragma unroll
            for (int e = 0; e < KK; e++) {
                float4 v = *(const float4*)&sst[e * HP + k];
                acc[e] += v.x * w0 + v.y * w1 + v.z * w2 + v.w * w3;
            }
        }
        for (int k = 248; k < H; k++) {
            float w = W[k * H + t];
            #pragma unroll
            for (int e = 0; e < KK; e++) acc[e] += sst[e * HP + k] * w;
        }
        float bb = b[t];
        #pragma unroll
        for (int e = 0; e < KK; e++) {
            acc[e] = fmaxf(acc[e] + bb, 0.f);
            hbuf[e * HP + t] = acc[e];
        }
    }
    __syncthreads();

    const int warp = t >> 5, lane = t & 31;
    {
        float s = 0.f, s2 = 0.f;
        for (int k = lane; k < H; k += 32) {
            float v = hbuf[warp * HP + k];
            s += v; s2 += v * v;
        }
        #pragma unroll
        for (int off = 16; off; off >>= 1) {
            s  += __shfl_xor_sync(0xffffffffu, s,  off);
            s2 += __shfl_xor_sync(0xffffffffu, s2, off);
        }
        if (lane == 0) {
            float mu = s * (1.f / H);
            st[warp * 2]     = mu;
            st[warp * 2 + 1] = rsqrtf(s2 * (1.f / H) - mu * mu + EPS_);
        }
    }
    __syncthreads();

    if (t < H) {
        float gg = g[t], bb = bt[t];
        #pragma unroll
        for (int e = 0; e < KK; e++) {
            float v = (acc[e] - st[e * 2]) * st[e * 2 + 1] * gg + bb;
            g_s1[((size_t)grp * KK + e) * H + t] = v;
        }
    }
}

// ---------------------------------------------------------------------------
// Kernel 2: fused per-group pair pipeline.
// core_out[p] = Wf^T s1[focal] + Wo^T s1[other]  (decomposed: 8 focal + 8 other
// partials instead of 56 full dot products), then LN -> ctx GEMM + LN,
// att1 GEMM + LN + att2 + sigmoid, effect accumulation.
// ---------------------------------------------------------------------------
__global__ __launch_bounds__(256, 1) void pair_kernel(
    const float* __restrict__ core_W, const float* __restrict__ core_b,
    const float* __restrict__ core_g, const float* __restrict__ core_bt,
    const float* __restrict__ ctx_W,  const float* __restrict__ ctx_b,
    const float* __restrict__ ctx_g,  const float* __restrict__ ctx_bt,
    const float* __restrict__ att_W1, const float* __restrict__ att_b1,
    const float* __restrict__ att_g,  const float* __restrict__ att_bt,
    const float* __restrict__ att_W2, const float* __restrict__ att_b2)
{
    extern __shared__ float sm[];
    float* s1s   = sm;                    // 8  * HP   = 2016
    float* coreb = s1s   + KK * HP;       // 56 * HP   = 14112
    float* ctxb  = coreb + NP * HP;       // 56 * HP   = 14112
    float* attb  = ctxb  + NP * HP;       // 56 * HA_  = 5600
    float* attv  = attb  + NP * HA_;      // 56
    float* stA   = attv  + NP;            // 56*2 (core mu/rstd)
    float* stC   = stA   + NP * 2;        // 56*2 (ctx mu/rstd)

    const int t = threadIdx.x;
    const int grp = blockIdx.x;
    const int warp = t >> 5, lane = t & 31;

    for (int i = t; i < KK * H; i += 256) {
        int r = i / H, c = i % H;
        s1s[r * HP + c] = g_s1[((size_t)grp * KK + r) * H + c];
    }
    __syncthreads();

    // ---- core GEMM (decomposed focal/other halves) ----
    if (t < H) {
        float fa[KK], oa[KK];
        #pragma unroll
        for (int e = 0; e < KK; e++) { fa[e] = 0.f; oa[e] = 0.f; }
        #pragma unroll 1
        for (int k = 0; k < 248; k += 4) {
            float wf0 = core_W[(k + 0) * H + t];
            float wf1 = core_W[(k + 1) * H + t];
            float wf2 = core_W[(k + 2) * H + t];
            float wf3 = core_W[(k + 3) * H + t];
            float wo0 = core_W[(k + 250) * H + t];
            float wo1 = core_W[(k + 251) * H + t];
            float wo2 = core_W[(k + 252) * H + t];
            float wo3 = core_W[(k + 253) * H + t];
            #pragma unroll
            for (int e = 0; e < KK; e++) {
                float4 v = *(const float4*)&s1s[e * HP + k];
                fa[e] += v.x * wf0 + v.y * wf1 + v.z * wf2 + v.w * wf3;
                oa[e] += v.x * wo0 + v.y * wo1 + v.z * wo2 + v.w * wo3;
            }
        }
        for (int k = 248; k < H; k++) {
            float wf = core_W[k * H + t];
            float wo = core_W[(k + 250) * H + t];
            #pragma unroll
            for (int e = 0; e < KK; e++) {
                float v = s1s[e * HP + k];
                fa[e] += v * wf;
                oa[e] += v * wo;
            }
        }
        float cb = core_b[t];
        #pragma unroll
        for (int p = 0; p < NP; p++) {
            const int i = p / 7, jj = p % 7;
            const int o = jj + (jj >= i);
            coreb[p * HP + t] = fmaxf(fa[i] + oa[o] + cb, 0.f);
        }
    }
    __syncthreads();

    // ---- core LN stats (warp per pair) ----
    for (int p = warp; p < NP; p += 8) {
        float s = 0.f, s2 = 0.f;
        for (int k = lane; k < H; k += 32) {
            float v = coreb[p * HP + k];
            s += v; s2 += v * v;
        }
        #pragma unroll
        for (int off = 16; off; off >>= 1) {
            s  += __shfl_xor_sync(0xffffffffu, s,  off);
            s2 += __shfl_xor_sync(0xffffffffu, s2, off);
        }
        if (lane == 0) {
            float mu = s * (1.f / H);
            stA[2 * p]     = mu;
            stA[2 * p + 1] = rsqrtf(s2 * (1.f / H) - mu * mu + EPS_);
        }
    }
    __syncthreads();

    // ---- normalize coreb in place ----
    if (t < H) {
        float gg = core_g[t], bb = core_bt[t];
        #pragma unroll
        for (int p = 0; p < NP; p++) {
            float v = coreb[p * HP + t];
            coreb[p * HP + t] = (v - stA[2 * p]) * stA[2 * p + 1] * gg + bb;
        }
    }
    __syncthreads();

    // ---- ctx GEMM (t<250) ----
    if (t < H) {
        float a2[NP];
        #pragma unroll
        for (int p = 0; p < NP; p++) a2[p] = 0.f;
        #pragma unroll 1
        for (int k = 0; k < 248; k += 4) {
            float w0 = ctx_W[(k + 0) * H + t];
            float w1 = ctx_W[(k + 1) * H + t];
            float w2 = ctx_W[(k + 2) * H + t];
            float w3 = ctx_W[(k + 3) * H + t];
            #pragma unroll
            for (int p = 0; p < NP; p++) {
                float4 c = *(const float4*)&coreb[p * HP + k];
                a2[p] += c.x * w0 + c.y * w1 + c.z * w2 + c.w * w3;
            }
        }
        for (int k = 248; k < H; k++) {
            float w = ctx_W[k * H + t];
            #pragma unroll
            for (int p = 0; p < NP; p++) a2[p] += coreb[p * HP + k] * w;
        }
        float cb = ctx_b[t];
        #pragma unroll
        for (int p = 0; p < NP; p++)
            ctxb[p * HP + t] = fmaxf(a2[p] + cb, 0.f);
    }

    // ---- att1 GEMM: 2 column-groups of 100 threads, 28 pairs each ----
    {
        const int ag = t / HA_;     // group 0 or 1 active
        const int ac = t % HA_;
        if (ag < 2) {
            float a3[NP / 2];
            #pragma unroll
            for (int pp = 0; pp < NP / 2; pp++) a3[pp] = 0.f;
            const int pbase = ag * (NP / 2);
            #pragma unroll 1
            for (int k = 0; k < 248; k += 4) {
                float w0 = att_W1[(k + 0) * HA_ + ac];
                float w1 = att_W1[(k + 1) * HA_ + ac];
                float w2 = att_W1[(k + 2) * HA_ + ac];
                float w3 = att_W1[(k + 3) * HA_ + ac];
                #pragma unroll
                for (int pp = 0; pp < NP / 2; pp++) {
                    float4 c = *(const float4*)&coreb[(pbase + pp) * HP + k];
                    a3[pp] += c.x * w0 + c.y * w1 + c.z * w2 + c.w * w3;
                }
            }
            for (int k = 248; k < H; k++) {
                float w = att_W1[k * HA_ + ac];
                #pragma unroll
                for (int pp = 0; pp < NP / 2; pp++)
                    a3[pp] += coreb[(pbase + pp) * HP + k] * w;
            }
            float b1 = att_b1[ac];
            #pragma unroll
            for (int pp = 0; pp < NP / 2; pp++)
                attb[(pbase + pp) * HA_ + ac] = tanhf(a3[pp] + b1);
        }
    }
    __syncthreads();

    // ---- ctx LN stats + att LN + att2 + sigmoid (warp per pair) ----
    for (int p = warp; p < NP; p += 8) {
        {   // ctx stats
            float s = 0.f, s2 = 0.f;
            for (int k = lane; k < H; k += 32) {
                float v = ctxb[p * HP + k];
                s += v; s2 += v * v;
            }
            #pragma unroll
            for (int off = 16; off; off >>= 1) {
                s  += __shfl_xor_sync(0xffffffffu, s,  off);
                s2 += __shfl_xor_sync(0xffffffffu, s2, off);
            }
            if (lane == 0) {
                float mu = s * (1.f / H);
                stC[2 * p]     = mu;
                stC[2 * p + 1] = rsqrtf(s2 * (1.f / H) - mu * mu + EPS_);
            }
        }
        {   // att LN + att2
            float s = 0.f, s2 = 0.f;
            for (int k = lane; k < HA_; k += 32) {
                float v = attb[p * HA_ + k];
                s += v; s2 += v * v;
            }
            #pragma unroll
            for (int off = 16; off; off >>= 1) {
                s  += __shfl_xor_sync(0xffffffffu, s,  off);
                s2 += __shfl_xor_sync(0xffffffffu, s2, off);
            }
            float mu = s * (1.f / HA_);
            float rs = rsqrtf(s2 * (1.f / HA_) - mu * mu + EPS_);
            float s3 = 0.f;
            for (int k = lane; k < HA_; k += 32) {
                float v = (attb[p * HA_ + k] - mu) * rs * att_g[k] + att_bt[k];
                s3 += v * att_W2[k];
            }
            #pragma unroll
            for (int off = 16; off; off >>= 1)
                s3 += __shfl_xor_sync(0xffffffffu, s3, off);
            if (lane == 0)
                attv[p] = 1.f / (1.f + expf(-(s3 + att_b2[0])));
        }
    }
    __syncthreads();

    // ---- effect accumulation ----
    if (t < H) {
        float gg = ctx_g[t], bb = ctx_bt[t];
        float eff[KK];
        #pragma unroll
        for (int e = 0; e < KK; e++) eff[e] = 0.f;
        #pragma unroll
        for (int p = 0; p < NP; p++) {
            const int i = p / 7;
            float v = ctxb[p * HP + t];
            v = (v - stC[2 * p]) * stC[2 * p + 1] * gg + bb;
            eff[i] += v * attv[p];
        }
        #pragma unroll
        for (int e = 0; e < KK; e++)
            g_eff[((size_t)grp * KK + e) * H + t] = eff[e];
    }
}

// ---------------------------------------------------------------------------
// Kernel 3: new_state = [s1, effect, x] @ out_W + out_b
// ---------------------------------------------------------------------------
__global__ __launch_bounds__(256, 1) void out_kernel(
    const float* __restrict__ x, const float* __restrict__ W,
    const float* __restrict__ b, float* __restrict__ out)
{
    __shared__ float tot[KK * CIN];   // 8*1076*4 = 34432 B
    const int t = threadIdx.x;
    const int grp = blockIdx.x;

    for (int i = t; i < KK * CIN; i += 256) {
        int r = i / CIN, k = i % CIN;
        size_t row = (size_t)grp * KK + r;
        float v;
        if (k < H)           v = g_s1[row * H + k];
        else if (k < 2 * H)  v = g_eff[row * H + (k - H)];
        else                 v = x[row * MM + (k - 2 * H)];
        tot[r * CIN + k] = v;
    }
    __syncthreads();

    if (t >= H) return;
    float acc[KK];
    #pragma unroll
    for (int e = 0; e < KK; e++) acc[e] = 0.f;
    #pragma unroll 1
    for (int k = 0; k < CIN; k += 4) {       // 1076 % 4 == 0
        float w0 = W[(k + 0) * H + t];
        float w1 = W[(k + 1) * H + t];
        float w2 = W[(k + 2) * H + t];
        float w3 = W[(k + 3) * H + t];
        #pragma unroll
        for (int e = 0; e < KK; e++) {
            float4 v = *(const float4*)&tot[e * CIN + k];
            acc[e] += v.x * w0 + v.y * w1 + v.z * w2 + v.w * w3;
        }
    }
    float bb = b[t];
    #pragma unroll
    for (int e = 0; e < KK; e++)
        out[((size_t)grp * KK + e) * H + t] = acc[e] + bb;
}

// ---------------------------------------------------------------------------
extern "C" void kernel_launch(void* const* d_in, const int* in_sizes, int n_in,
                              void* d_out, int out_size)
{
    const float* x       = (const float*)d_in[0];
    const float* state   = (const float*)d_in[1];
    const float* enc_W   = (const float*)d_in[2];
    const float* enc_b   = (const float*)d_in[3];
    const float* enc_g   = (const float*)d_in[4];
    const float* enc_bt  = (const float*)d_in[5];
    const float* core_W  = (const float*)d_in[6];
    const float* core_b  = (const float*)d_in[7];
    const float* core_g  = (const float*)d_in[8];
    const float* core_bt = (const float*)d_in[9];
    const float* ctx_W   = (const float*)d_in[10];
    const float* ctx_b   = (const float*)d_in[11];
    const float* ctx_g   = (const float*)d_in[12];
    const float* ctx_bt  = (const float*)d_in[13];
    const float* att_W1  = (const float*)d_in[14];
    const float* att_b1  = (const float*)d_in[15];
    const float* att_g   = (const float*)d_in[16];
    const float* att_bt  = (const float*)d_in[17];
    const float* att_W2  = (const float*)d_in[18];
    const float* att_b2  = (const float*)d_in[19];
    const float* out_W   = (const float*)d_in[20];
    const float* out_b   = (const float*)d_in[21];
    float* out = (float*)d_out;

    const int smB = (KK * HP + 2 * NP * HP + NP * HA_ + NP + 4 * NP) * (int)sizeof(float);
    cudaFuncSetAttribute(pair_kernel, cudaFuncAttributeMaxDynamicSharedMemorySize, smB);

    enc_kernel<<<NB, 256>>>(state, enc_W, enc_b, enc_g, enc_bt);
    pair_kernel<<<NB, 256, smB>>>(core_W, core_b, core_g, core_bt,
                                  ctx_W, ctx_b, ctx_g, ctx_bt,
                                  att_W1, att_b1, att_g, att_bt,
                                  att_W2, att_b2);
    out_kernel<<<NB, 256>>>(x, out_W, out_b, out);
}

// round 4
// speedup vs baseline: 1.0814x; 1.0814x over previous
#include <cuda_runtime.h>
#include <math.h>

#define KK   8
#define H    250
#define HP   252          // padded row stride (16B-aligned: 252*4=1008=63*16)
#define NP   56           // K*(K-1) pairs per group
#define HA_  100
#define MM   576
#define NB   2048         // batch groups
#define BK   (NB*KK)
#define CIN  1076         // 250 + 250 + 576
#define EPS_ 1e-5f

typedef unsigned long long u64t;

// ---------------------------------------------------------------------------
// f32x2 packed-FMA helpers (FFMA2 — PTX-only on sm_103a)
// ---------------------------------------------------------------------------
__device__ __forceinline__ u64t pack2(float lo, float hi) {
    u64t r;
    asm("mov.b64 %0, {%1, %2};" : "=l"(r) : "f"(lo), "f"(hi));
    return r;
}
__device__ __forceinline__ void fma2(u64t& d, u64t a, u64t b) {
    asm("fma.rn.f32x2 %0, %1, %2, %0;" : "+l"(d) : "l"(a), "l"(b));
}
__device__ __forceinline__ float sum2(u64t v) {
    float lo, hi;
    asm("mov.b64 {%0, %1}, %2;" : "=f"(lo), "=f"(hi) : "l"(v));
    return lo + hi;
}

// scratch (allocation-free rule: device globals)
__device__ float g_s1[(size_t)BK * H];
__device__ float g_eff[(size_t)BK * H];

// ---------------------------------------------------------------------------
// Kernel 1: s1 = LN(relu(state @ enc_W + enc_b)); 16 rows (2 groups) / block
// ---------------------------------------------------------------------------
#define ER 16
__global__ __launch_bounds__(256, 2) void enc_kernel(
    const float* __restrict__ state, const float* __restrict__ W,
    const float* __restrict__ b, const float* __restrict__ g,
    const float* __restrict__ bt)
{
    __shared__ float sst[ER * HP];
    __shared__ float st[ER * 2];

    const int t = threadIdx.x;
    const size_t base = (size_t)blockIdx.x * ER;   // first global row
    const float* srow = state + base * H;

    for (int i = t; i < ER * H; i += 256) {
        int r = i / H, c = i % H;
        sst[r * HP + c] = srow[i];
    }
    __syncthreads();

    float relu_v[ER];
    if (t < H) {
        u64t acc[ER];
        #pragma unroll
        for (int e = 0; e < ER; e++) acc[e] = 0ull;
        #pragma unroll 1
        for (int k = 0; k < 248; k += 4) {
            u64t w01 = pack2(W[(k + 0) * H + t], W[(k + 1) * H + t]);
            u64t w23 = pack2(W[(k + 2) * H + t], W[(k + 3) * H + t]);
            #pragma unroll
            for (int e = 0; e < ER; e++) {
                ulonglong2 v = *(const ulonglong2*)&sst[e * HP + k];
                fma2(acc[e], v.x, w01);
                fma2(acc[e], v.y, w23);
            }
        }
        u64t wt = pack2(W[248 * H + t], W[249 * H + t]);
        #pragma unroll
        for (int e = 0; e < ER; e++) {
            u64t v = *(const u64t*)&sst[e * HP + 248];
            fma2(acc[e], v, wt);
        }
        float bb = b[t];
        #pragma unroll
        for (int e = 0; e < ER; e++) relu_v[e] = fmaxf(sum2(acc[e]) + bb, 0.f);
    }
    __syncthreads();
    // reuse sst as relu buffer
    if (t < H) {
        #pragma unroll
        for (int e = 0; e < ER; e++) sst[e * HP + t] = relu_v[e];
    }
    __syncthreads();

    const int warp = t >> 5, lane = t & 31;
    for (int r = warp; r < ER; r += 8) {
        float s = 0.f, s2 = 0.f;
        for (int k = lane; k < H; k += 32) {
            float v = sst[r * HP + k];
            s += v; s2 += v * v;
        }
        #pragma unroll
        for (int off = 16; off; off >>= 1) {
            s  += __shfl_xor_sync(0xffffffffu, s,  off);
            s2 += __shfl_xor_sync(0xffffffffu, s2, off);
        }
        if (lane == 0) {
            float mu = s * (1.f / H);
            st[r * 2]     = mu;
            st[r * 2 + 1] = rsqrtf(s2 * (1.f / H) - mu * mu + EPS_);
        }
    }
    __syncthreads();

    if (t < H) {
        float gg = g[t], bb = bt[t];
        #pragma unroll
        for (int e = 0; e < ER; e++) {
            float v = (relu_v[e] - st[e * 2]) * st[e * 2 + 1] * gg + bb;
            g_s1[(base + e) * H + t] = v;
        }
    }
}

// ---------------------------------------------------------------------------
// Kernel 2: fused per-group pair pipeline, 512 threads.
//   core decomposed: half 0 computes focal partials, half 1 other partials.
//   ctx: 2 halves x 28 pairs.  att1: 4 groups x 14 pairs.
// ---------------------------------------------------------------------------
__global__ __launch_bounds__(512, 1) void pair_kernel(
    const float* __restrict__ core_W, const float* __restrict__ core_b,
    const float* __restrict__ core_g, const float* __restrict__ core_bt,
    const float* __restrict__ ctx_W,  const float* __restrict__ ctx_b,
    const float* __restrict__ ctx_g,  const float* __restrict__ ctx_bt,
    const float* __restrict__ att_W1, const float* __restrict__ att_b1,
    const float* __restrict__ att_g,  const float* __restrict__ att_bt,
    const float* __restrict__ att_W2, const float* __restrict__ att_b2)
{
    extern __shared__ float sm[];
    float* s1s   = sm;                    // 8  * HP
    float* fbuf  = s1s   + KK * HP;       // 8  * HP  (focal partials)
    float* obuf  = fbuf  + KK * HP;       // 8  * HP  (other partials)
    float* coreb = obuf  + KK * HP;       // 56 * HP
    float* ctxb  = coreb + NP * HP;       // 56 * HP
    float* attb  = ctxb  + NP * HP;       // 56 * HA_
    float* attv  = attb  + NP * HA_;      // 56
    float* stA   = attv  + NP;            // 56*2 (core mu/rstd)
    float* stC   = stA   + NP * 2;        // 56*2 (ctx mu/rstd)

    const int t = threadIdx.x;
    const int grp = blockIdx.x;
    const int warp = t >> 5, lane = t & 31;

    for (int i = t; i < KK * H; i += 512) {
        int r = i / H, c = i % H;
        s1s[r * HP + c] = g_s1[((size_t)grp * KK + r) * H + c];
    }
    __syncthreads();

    // ---- core GEMM, decomposed focal/other across the two 256-thread halves
    {
        const int h = t >> 8;          // 0: focal rows 0..249 ; 1: other rows 250..499
        const int c = t & 255;
        if (c < H) {
            const float* Wd = core_W + (h ? 250 * H : 0);
            u64t acc[KK];
            #pragma unroll
            for (int e = 0; e < KK; e++) acc[e] = 0ull;
            #pragma unroll 1
            for (int k = 0; k < 248; k += 4) {
                u64t w01 = pack2(Wd[(k + 0) * H + c], Wd[(k + 1) * H + c]);
                u64t w23 = pack2(Wd[(k + 2) * H + c], Wd[(k + 3) * H + c]);
                #pragma unroll
                for (int e = 0; e < KK; e++) {
                    ulonglong2 v = *(const ulonglong2*)&s1s[e * HP + k];
                    fma2(acc[e], v.x, w01);
                    fma2(acc[e], v.y, w23);
                }
            }
            u64t wt = pack2(Wd[248 * H + c], Wd[249 * H + c]);
            #pragma unroll
            for (int e = 0; e < KK; e++) {
                u64t v = *(const u64t*)&s1s[e * HP + 248];
                fma2(acc[e], v, wt);
            }
            float* dst = h ? obuf : fbuf;
            #pragma unroll
            for (int e = 0; e < KK; e++) dst[e * HP + c] = sum2(acc[e]);
        }
    }
    __syncthreads();

    // ---- assemble coreb[p] = relu(focal[i] + other[o] + bias) ----
    for (int i = t; i < NP * H; i += 512) {
        int p = i / H, c = i % H;
        int fi = p / 7, jj = p % 7;
        int o = jj + (jj >= fi);
        coreb[p * HP + c] = fmaxf(fbuf[fi * HP + c] + obuf[o * HP + c] + core_b[c], 0.f);
    }
    __syncthreads();

    // ---- core LN stats (warp per pair, 16 warps) ----
    for (int p = warp; p < NP; p += 16) {
        float s = 0.f, s2 = 0.f;
        for (int k = lane; k < H; k += 32) {
            float v = coreb[p * HP + k];
            s += v; s2 += v * v;
        }
        #pragma unroll
        for (int off = 16; off; off >>= 1) {
            s  += __shfl_xor_sync(0xffffffffu, s,  off);
            s2 += __shfl_xor_sync(0xffffffffu, s2, off);
        }
        if (lane == 0) {
            float mu = s * (1.f / H);
            stA[2 * p]     = mu;
            stA[2 * p + 1] = rsqrtf(s2 * (1.f / H) - mu * mu + EPS_);
        }
    }
    __syncthreads();

    // ---- normalize coreb in place ----
    for (int i = t; i < NP * H; i += 512) {
        int p = i / H, c = i % H;
        float v = coreb[p * HP + c];
        coreb[p * HP + c] = (v - stA[2 * p]) * stA[2 * p + 1] * core_g[c] + core_bt[c];
    }
    __syncthreads();

    // ---- ctx GEMM: 2 halves x 28 pairs ----
    {
        const int h = t >> 8;
        const int c = t & 255;
        if (c < H) {
            const int pbase = h * 28;
            u64t acc[28];
            #pragma unroll
            for (int pp = 0; pp < 28; pp++) acc[pp] = 0ull;
            #pragma unroll 1
            for (int k = 0; k < 248; k += 4) {
                u64t w01 = pack2(ctx_W[(k + 0) * H + c], ctx_W[(k + 1) * H + c]);
                u64t w23 = pack2(ctx_W[(k + 2) * H + c], ctx_W[(k + 3) * H + c]);
                #pragma unroll
                for (int pp = 0; pp < 28; pp++) {
                    ulonglong2 v = *(const ulonglong2*)&coreb[(pbase + pp) * HP + k];
                    fma2(acc[pp], v.x, w01);
                    fma2(acc[pp], v.y, w23);
                }
            }
            u64t wt = pack2(ctx_W[248 * H + c], ctx_W[249 * H + c]);
            #pragma unroll
            for (int pp = 0; pp < 28; pp++) {
                u64t v = *(const u64t*)&coreb[(pbase + pp) * HP + 248];
                fma2(acc[pp], v, wt);
            }
            float cb = ctx_b[c];
            #pragma unroll
            for (int pp = 0; pp < 28; pp++)
                ctxb[(pbase + pp) * HP + c] = fmaxf(sum2(acc[pp]) + cb, 0.f);
        }
    }

    // ---- att1 GEMM: 4 groups x 14 pairs (no sync needed w.r.t. ctx: reads coreb only)
    {
        const int ag = t >> 7;          // 0..3
        const int ac = t & 127;
        if (ac < HA_) {
            const int pbase = ag * 14;
            u64t acc[14];
            #pragma unroll
            for (int pp = 0; pp < 14; pp++) acc[pp] = 0ull;
            #pragma unroll 1
            for (int k = 0; k < 248; k += 4) {
                u64t w01 = pack2(att_W1[(k + 0) * HA_ + ac], att_W1[(k + 1) * HA_ + ac]);
                u64t w23 = pack2(att_W1[(k + 2) * HA_ + ac], att_W1[(k + 3) * HA_ + ac]);
                #pragma unroll
                for (int pp = 0; pp < 14; pp++) {
                    ulonglong2 v = *(const ulonglong2*)&coreb[(pbase + pp) * HP + k];
                    fma2(acc[pp], v.x, w01);
                    fma2(acc[pp], v.y, w23);
                }
            }
            u64t wt = pack2(att_W1[248 * HA_ + ac], att_W1[249 * HA_ + ac]);
            #pragma unroll
            for (int pp = 0; pp < 14; pp++) {
                u64t v = *(const u64t*)&coreb[(pbase + pp) * HP + 248];
                fma2(acc[pp], v, wt);
            }
            float b1 = att_b1[ac];
            #pragma unroll
            for (int pp = 0; pp < 14; pp++)
                attb[(pbase + pp) * HA_ + ac] = tanhf(sum2(acc[pp]) + b1);
        }
    }
    __syncthreads();

    // ---- ctx LN stats + att LN + att2 + sigmoid (warp per pair, 16 warps) ----
    for (int p = warp; p < NP; p += 16) {
        {   // ctx stats
            float s = 0.f, s2 = 0.f;
            for (int k = lane; k < H; k += 32) {
                float v = ctxb[p * HP + k];
                s += v; s2 += v * v;
            }
            #pragma unroll
            for (int off = 16; off; off >>= 1) {
                s  += __shfl_xor_sync(0xffffffffu, s,  off);
                s2 += __shfl_xor_sync(0xffffffffu, s2, off);
            }
            if (lane == 0) {
                float mu = s * (1.f / H);
                stC[2 * p]     = mu;
                stC[2 * p + 1] = rsqrtf(s2 * (1.f / H) - mu * mu + EPS_);
            }
        }
        {   // att LN + att2 dot + sigmoid
            float s = 0.f, s2 = 0.f;
            for (int k = lane; k < HA_; k += 32) {
                float v = attb[p * HA_ + k];
                s += v; s2 += v * v;
            }
            #pragma unroll
            for (int off = 16; off; off >>= 1) {
                s  += __shfl_xor_sync(0xffffffffu, s,  off);
                s2 += __shfl_xor_sync(0xffffffffu, s2, off);
            }
            float mu = s * (1.f / HA_);
            float rs = rsqrtf(s2 * (1.f / HA_) - mu * mu + EPS_);
            float s3 = 0.f;
            for (int k = lane; k < HA_; k += 32) {
                float v = (attb[p * HA_ + k] - mu) * rs * att_g[k] + att_bt[k];
                s3 += v * att_W2[k];
            }
            #pragma unroll
            for (int off = 16; off; off >>= 1)
                s3 += __shfl_xor_sync(0xffffffffu, s3, off);
            if (lane == 0)
                attv[p] = 1.f / (1.f + expf(-(s3 + att_b2[0])));
        }
    }
    __syncthreads();

    // ---- effect accumulation ----
    if (t < H) {
        float gg = ctx_g[t], bb = ctx_bt[t];
        float eff[KK];
        #pragma unroll
        for (int e = 0; e < KK; e++) eff[e] = 0.f;
        #pragma unroll
        for (int p = 0; p < NP; p++) {
            const int i = p / 7;
            float v = ctxb[p * HP + t];
            v = (v - stC[2 * p]) * stC[2 * p + 1] * gg + bb;
            eff[i] += v * attv[p];
        }
        #pragma unroll
        for (int e = 0; e < KK; e++)
            g_eff[((size_t)grp * KK + e) * H + t] = eff[e];
    }
}

// ---------------------------------------------------------------------------
// Kernel 3: new_state = [s1, effect, x] @ out_W + out_b ; 16 rows / block
// ---------------------------------------------------------------------------
#define OR_ 16
__global__ __launch_bounds__(256, 2) void out_kernel(
    const float* __restrict__ x, const float* __restrict__ W,
    const float* __restrict__ b, float* __restrict__ out)
{
    extern __shared__ float tot[];   // OR_ * CIN floats (row stride 4304B, 16B-mult)
    const int t = threadIdx.x;
    const size_t base = (size_t)blockIdx.x * OR_;

    for (int i = t; i < OR_ * CIN; i += 256) {
        int r = i / CIN, k = i % CIN;
        size_t row = base + r;
        float v;
        if (k < H)           v = g_s1[row * H + k];
        else if (k < 2 * H)  v = g_eff[row * H + (k - H)];
        else                 v = x[row * MM + (k - 2 * H)];
        tot[r * CIN + k] = v;
    }
    __syncthreads();

    if (t >= H) return;
    u64t acc[OR_];
    #pragma unroll
    for (int e = 0; e < OR_; e++) acc[e] = 0ull;
    #pragma unroll 1
    for (int k = 0; k < CIN; k += 4) {       // 1076 % 4 == 0, no tail
        u64t w01 = pack2(W[(k + 0) * H + t], W[(k + 1) * H + t]);
        u64t w23 = pack2(W[(k + 2) * H + t], W[(k + 3) * H + t]);
        #pragma unroll
        for (int e = 0; e < OR_; e++) {
            ulonglong2 v = *(const ulonglong2*)&tot[e * CIN + k];
            fma2(acc[e], v.x, w01);
            fma2(acc[e], v.y, w23);
        }
    }
    float bb = b[t];
    #pragma unroll
    for (int e = 0; e < OR_; e++)
        out[(base + e) * H + t] = sum2(acc[e]) + bb;
}

// ---------------------------------------------------------------------------
extern "C" void kernel_launch(void* const* d_in, const int* in_sizes, int n_in,
                              void* d_out, int out_size)
{
    const float* x       = (const float*)d_in[0];
    const float* state   = (const float*)d_in[1];
    const float* enc_W   = (const float*)d_in[2];
    const float* enc_b   = (const float*)d_in[3];
    const float* enc_g   = (const float*)d_in[4];
    const float* enc_bt  = (const float*)d_in[5];
    const float* core_W  = (const float*)d_in[6];
    const float* core_b  = (const float*)d_in[7];
    const float* core_g  = (const float*)d_in[8];
    const float* core_bt = (const float*)d_in[9];
    const float* ctx_W   = (const float*)d_in[10];
    const float* ctx_b   = (const float*)d_in[11];
    const float* ctx_g   = (const float*)d_in[12];
    const float* ctx_bt  = (const float*)d_in[13];
    const float* att_W1  = (const float*)d_in[14];
    const float* att_b1  = (const float*)d_in[15];
    const float* att_g   = (const float*)d_in[16];
    const float* att_bt  = (const float*)d_in[17];
    const float* att_W2  = (const float*)d_in[18];
    const float* att_b2  = (const float*)d_in[19];
    const float* out_W   = (const float*)d_in[20];
    const float* out_b   = (const float*)d_in[21];
    float* out = (float*)d_out;

    static int configured = 0;
    const int pair_smB = (3 * KK * HP + 2 * NP * HP + NP * HA_ + NP + 4 * NP) * (int)sizeof(float);
    const int out_smB  = OR_ * CIN * (int)sizeof(float);
    if (!configured) {
        cudaFuncSetAttribute(pair_kernel, cudaFuncAttributeMaxDynamicSharedMemorySize, pair_smB);
        cudaFuncSetAttribute(out_kernel,  cudaFuncAttributeMaxDynamicSharedMemorySize, out_smB);
        configured = 1;
    }

    enc_kernel<<<BK / ER, 256>>>(state, enc_W, enc_b, enc_g, enc_bt);
    pair_kernel<<<NB, 512, pair_smB>>>(core_W, core_b, core_g, core_bt,
                                       ctx_W, ctx_b, ctx_g, ctx_bt,
                                       att_W1, att_b1, att_g, att_bt,
                                       att_W2, att_b2);
    out_kernel<<<BK / OR_, 256, out_smB>>>(x, out_W, out_b, out);
}

// round 8
// speedup vs baseline: 1.0898x; 1.0078x over previous
#include <cuda_runtime.h>
#include <math.h>

#define KK   8
#define H    250
#define HP   252          // padded row stride (16B-aligned)
#define NP   56           // K*(K-1) pairs per group
#define HA_  100
#define MM   576
#define NB   2048         // batch groups
#define BK   (NB*KK)
#define CIN  1076         // 250 + 250 + 576
#define EPS_ 1e-5f

typedef unsigned long long u64t;

// f32x2 packed-FMA helpers (FFMA2 — PTX-only on sm_103a)
__device__ __forceinline__ u64t pack2(float lo, float hi) {
    u64t r;
    asm("mov.b64 %0, {%1, %2};" : "=l"(r) : "f"(lo), "f"(hi));
    return r;
}
__device__ __forceinline__ void fma2(u64t& d, u64t a, u64t b) {
    asm("fma.rn.f32x2 %0, %1, %2, %0;" : "+l"(d) : "l"(a), "l"(b));
}
__device__ __forceinline__ float sum2(u64t v) {
    float lo, hi;
    asm("mov.b64 {%0, %1}, %2;" : "=f"(lo), "=f"(hi) : "l"(v));
    return lo + hi;
}

// scratch (allocation-free rule: device globals)
__device__ float g_s1[(size_t)BK * H];
__device__ float g_eff[(size_t)BK * H];

// ---------------------------------------------------------------------------
// Kernel 1: s1 = LN(relu(state @ enc_W + enc_b)); 16 rows / block.
// Weight loads software-pipelined one 8-k chunk ahead.
// ---------------------------------------------------------------------------
#define ER 16
__global__ __launch_bounds__(256, 2) void enc_kernel(
    const float* __restrict__ state, const float* __restrict__ W,
    const float* __restrict__ b, const float* __restrict__ g,
    const float* __restrict__ bt)
{
    __shared__ float sst[ER * HP];
    __shared__ float st[ER * 2];

    const int t = threadIdx.x;
    const size_t base = (size_t)blockIdx.x * ER;
    const float* srow = state + base * H;

    for (int i = t; i < ER * H; i += 256) {
        int r = i / H, c = i % H;
        sst[r * HP + c] = srow[i];
    }
    __syncthreads();

    float relu_v[ER];
    if (t < H) {
        const float* Wc = W + t;
        u64t acc[ER];
        #pragma unroll
        for (int e = 0; e < ER; e++) acc[e] = 0ull;

        float wa[8];
        #pragma unroll
        for (int j = 0; j < 8; j++) wa[j] = Wc[j * H];
        #pragma unroll 1
        for (int k = 0; k < 240; k += 8) {
            float wb[8];
            #pragma unroll
            for (int j = 0; j < 8; j++) wb[j] = Wc[(k + 8 + j) * H];
            u64t w01 = pack2(wa[0], wa[1]), w23 = pack2(wa[2], wa[3]);
            u64t w45 = pack2(wa[4], wa[5]), w67 = pack2(wa[6], wa[7]);
            #pragma unroll
            for (int e = 0; e < ER; e++) {
                ulonglong2 v0 = *(const ulonglong2*)&sst[e * HP + k];
                ulonglong2 v1 = *(const ulonglong2*)&sst[e * HP + k + 4];
                fma2(acc[e], v0.x, w01); fma2(acc[e], v0.y, w23);
                fma2(acc[e], v1.x, w45); fma2(acc[e], v1.y, w67);
            }
            #pragma unroll
            for (int j = 0; j < 8; j++) wa[j] = wb[j];
        }
        {   // k = 240..247 (already in wa)
            u64t w01 = pack2(wa[0], wa[1]), w23 = pack2(wa[2], wa[3]);
            u64t w45 = pack2(wa[4], wa[5]), w67 = pack2(wa[6], wa[7]);
            #pragma unroll
            for (int e = 0; e < ER; e++) {
                ulonglong2 v0 = *(const ulonglong2*)&sst[e * HP + 240];
                ulonglong2 v1 = *(const ulonglong2*)&sst[e * HP + 244];
                fma2(acc[e], v0.x, w01); fma2(acc[e], v0.y, w23);
                fma2(acc[e], v1.x, w45); fma2(acc[e], v1.y, w67);
            }
        }
        {   // tail k = 248,249
            u64t wt = pack2(Wc[248 * H], Wc[249 * H]);
            #pragma unroll
            for (int e = 0; e < ER; e++) {
                u64t v = *(const u64t*)&sst[e * HP + 248];
                fma2(acc[e], v, wt);
            }
        }
        float bb = b[t];
        #pragma unroll
        for (int e = 0; e < ER; e++) relu_v[e] = fmaxf(sum2(acc[e]) + bb, 0.f);
    }
    __syncthreads();
    if (t < H) {
        #pragma unroll
        for (int e = 0; e < ER; e++) sst[e * HP + t] = relu_v[e];
    }
    __syncthreads();

    const int warp = t >> 5, lane = t & 31;
    for (int r = warp; r < ER; r += 8) {
        float s = 0.f, s2 = 0.f;
        for (int k = lane; k < H; k += 32) {
            float v = sst[r * HP + k];
            s += v; s2 += v * v;
        }
        #pragma unroll
        for (int off = 16; off; off >>= 1) {
            s  += __shfl_xor_sync(0xffffffffu, s,  off);
            s2 += __shfl_xor_sync(0xffffffffu, s2, off);
        }
        if (lane == 0) {
            float mu = s * (1.f / H);
            st[r * 2]     = mu;
            st[r * 2 + 1] = rsqrtf(s2 * (1.f / H) - mu * mu + EPS_);
        }
    }
    __syncthreads();

    if (t < H) {
        float gg = g[t], bb = bt[t];
        #pragma unroll
        for (int e = 0; e < ER; e++) {
            float v = (relu_v[e] - st[e * 2]) * st[e * 2 + 1] * gg + bb;
            g_s1[(base + e) * H + t] = v;
        }
    }
}

// ---------------------------------------------------------------------------
// Kernel 2: fused per-group pair pipeline, 512 threads, pipelined weights.
// ---------------------------------------------------------------------------
__global__ __launch_bounds__(512, 1) void pair_kernel(
    const float* __restrict__ core_W, const float* __restrict__ core_b,
    const float* __restrict__ core_g, const float* __restrict__ core_bt,
    const float* __restrict__ ctx_W,  const float* __restrict__ ctx_b,
    const float* __restrict__ ctx_g,  const float* __restrict__ ctx_bt,
    const float* __restrict__ att_W1, const float* __restrict__ att_b1,
    const float* __restrict__ att_g,  const float* __restrict__ att_bt,
    const float* __restrict__ att_W2, const float* __restrict__ att_b2)
{
    extern __shared__ float sm[];
    float* s1s   = sm;                    // 8  * HP
    float* fbuf  = s1s   + KK * HP;       // 8  * HP
    float* obuf  = fbuf  + KK * HP;       // 8  * HP
    float* coreb = obuf  + KK * HP;       // 56 * HP
    float* ctxb  = coreb + NP * HP;       // 56 * HP
    float* attb  = ctxb  + NP * HP;       // 56 * HA_
    float* attv  = attb  + NP * HA_;      // 56
    float* stA   = attv  + NP;            // 56*2
    float* stC   = stA   + NP * 2;        // 56*2

    const int t = threadIdx.x;
    const int grp = blockIdx.x;
    const int warp = t >> 5, lane = t & 31;

    for (int i = t; i < KK * H; i += 512) {
        int r = i / H, c = i % H;
        s1s[r * HP + c] = g_s1[((size_t)grp * KK + r) * H + c];
    }
    __syncthreads();

    // ---- core GEMM, decomposed focal/other across two 256-thread halves ----
    {
        const int h = t >> 8;
        const int c = t & 255;
        if (c < H) {
            const float* Wc = core_W + (h ? 250 * H : 0) + c;
            u64t acc[KK];
            #pragma unroll
            for (int e = 0; e < KK; e++) acc[e] = 0ull;

            float wa[8];
            #pragma unroll
            for (int j = 0; j < 8; j++) wa[j] = Wc[j * H];
            #pragma unroll 1
            for (int k = 0; k < 240; k += 8) {
                float wb[8];
                #pragma unroll
                for (int j = 0; j < 8; j++) wb[j] = Wc[(k + 8 + j) * H];
                u64t w01 = pack2(wa[0], wa[1]), w23 = pack2(wa[2], wa[3]);
                u64t w45 = pack2(wa[4], wa[5]), w67 = pack2(wa[6], wa[7]);
                #pragma unroll
                for (int e = 0; e < KK; e++) {
                    ulonglong2 v0 = *(const ulonglong2*)&s1s[e * HP + k];
                    ulonglong2 v1 = *(const ulonglong2*)&s1s[e * HP + k + 4];
                    fma2(acc[e], v0.x, w01); fma2(acc[e], v0.y, w23);
                    fma2(acc[e], v1.x, w45); fma2(acc[e], v1.y, w67);
                }
                #pragma unroll
                for (int j = 0; j < 8; j++) wa[j] = wb[j];
            }
            {
                u64t w01 = pack2(wa[0], wa[1]), w23 = pack2(wa[2], wa[3]);
                u64t w45 = pack2(wa[4], wa[5]), w67 = pack2(wa[6], wa[7]);
                #pragma unroll
                for (int e = 0; e < KK; e++) {
                    ulonglong2 v0 = *(const ulonglong2*)&s1s[e * HP + 240];
                    ulonglong2 v1 = *(const ulonglong2*)&s1s[e * HP + 244];
                    fma2(acc[e], v0.x, w01); fma2(acc[e], v0.y, w23);
                    fma2(acc[e], v1.x, w45); fma2(acc[e], v1.y, w67);
                }
            }
            {
                u64t wt = pack2(Wc[248 * H], Wc[249 * H]);
                #pragma unroll
                for (int e = 0; e < KK; e++) {
                    u64t v = *(const u64t*)&s1s[e * HP + 248];
                    fma2(acc[e], v, wt);
                }
            }
            float* dst = h ? obuf : fbuf;
            #pragma unroll
            for (int e = 0; e < KK; e++) dst[e * HP + c] = sum2(acc[e]);
        }
    }
    __syncthreads();

    // ---- assemble coreb[p] = relu(focal[i] + other[o] + bias) ----
    for (int i = t; i < NP * H; i += 512) {
        int p = i / H, c = i % H;
        int fi = p / 7, jj = p % 7;
        int o = jj + (jj >= fi);
        coreb[p * HP + c] = fmaxf(fbuf[fi * HP + c] + obuf[o * HP + c] + core_b[c], 0.f);
    }
    __syncthreads();

    // ---- core LN stats (warp per pair, 16 warps) ----
    for (int p = warp; p < NP; p += 16) {
        float s = 0.f, s2 = 0.f;
        for (int k = lane; k < H; k += 32) {
            float v = coreb[p * HP + k];
            s += v; s2 += v * v;
        }
        #pragma unroll
        for (int off = 16; off; off >>= 1) {
            s  += __shfl_xor_sync(0xffffffffu, s,  off);
            s2 += __shfl_xor_sync(0xffffffffu, s2, off);
        }
        if (lane == 0) {
            float mu = s * (1.f / H);
            stA[2 * p]     = mu;
            stA[2 * p + 1] = rsqrtf(s2 * (1.f / H) - mu * mu + EPS_);
        }
    }
    __syncthreads();

    // ---- normalize coreb in place ----
    for (int i = t; i < NP * H; i += 512) {
        int p = i / H, c = i % H;
        float v = coreb[p * HP + c];
        coreb[p * HP + c] = (v - stA[2 * p]) * stA[2 * p + 1] * core_g[c] + core_bt[c];
    }
    __syncthreads();

    // ---- ctx GEMM: 2 halves x 28 pairs, pipelined ----
    {
        const int h = t >> 8;
        const int c = t & 255;
        if (c < H) {
            const int pbase = h * 28;
            const float* Wc = ctx_W + c;
            u64t acc[28];
            #pragma unroll
            for (int pp = 0; pp < 28; pp++) acc[pp] = 0ull;

            float wa[8];
            #pragma unroll
            for (int j = 0; j < 8; j++) wa[j] = Wc[j * H];
            #pragma unroll 1
            for (int k = 0; k < 240; k += 8) {
                float wb[8];
                #pragma unroll
                for (int j = 0; j < 8; j++) wb[j] = Wc[(k + 8 + j) * H];
                u64t w01 = pack2(wa[0], wa[1]), w23 = pack2(wa[2], wa[3]);
                u64t w45 = pack2(wa[4], wa[5]), w67 = pack2(wa[6], wa[7]);
                #pragma unroll
                for (int pp = 0; pp < 28; pp++) {
                    ulonglong2 v0 = *(const ulonglong2*)&coreb[(pbase + pp) * HP + k];
                    ulonglong2 v1 = *(const ulonglong2*)&coreb[(pbase + pp) * HP + k + 4];
                    fma2(acc[pp], v0.x, w01); fma2(acc[pp], v0.y, w23);
                    fma2(acc[pp], v1.x, w45); fma2(acc[pp], v1.y, w67);
                }
                #pragma unroll
                for (int j = 0; j < 8; j++) wa[j] = wb[j];
            }
            {
                u64t w01 = pack2(wa[0], wa[1]), w23 = pack2(wa[2], wa[3]);
                u64t w45 = pack2(wa[4], wa[5]), w67 = pack2(wa[6], wa[7]);
                #pragma unroll
                for (int pp = 0; pp < 28; pp++) {
                    ulonglong2 v0 = *(const ulonglong2*)&coreb[(pbase + pp) * HP + 240];
                    ulonglong2 v1 = *(const ulonglong2*)&coreb[(pbase + pp) * HP + 244];
                    fma2(acc[pp], v0.x, w01); fma2(acc[pp], v0.y, w23);
                    fma2(acc[pp], v1.x, w45); fma2(acc[pp], v1.y, w67);
                }
            }
            {
                u64t wt = pack2(Wc[248 * H], Wc[249 * H]);
                #pragma unroll
                for (int pp = 0; pp < 28; pp++) {
                    u64t v = *(const u64t*)&coreb[(pbase + pp) * HP + 248];
                    fma2(acc[pp], v, wt);
                }
            }
            float cb = ctx_b[c];
            #pragma unroll
            for (int pp = 0; pp < 28; pp++)
                ctxb[(pbase + pp) * HP + c] = fmaxf(sum2(acc[pp]) + cb, 0.f);
        }
    }

    // ---- att1 GEMM: 4 groups x 14 pairs, pipelined (reads coreb only) ----
    {
        const int ag = t >> 7;
        const int ac = t & 127;
        if (ac < HA_) {
            const int pbase = ag * 14;
            const float* Wc = att_W1 + ac;
            u64t acc[14];
            #pragma unroll
            for (int pp = 0; pp < 14; pp++) acc[pp] = 0ull;

            float wa[8];
            #pragma unroll
            for (int j = 0; j < 8; j++) wa[j] = Wc[j * HA_];
            #pragma unroll 1
            for (int k = 0; k < 240; k += 8) {
                float wb[8];
                #pragma unroll
                for (int j = 0; j < 8; j++) wb[j] = Wc[(k + 8 + j) * HA_];
                u64t w01 = pack2(wa[0], wa[1]), w23 = pack2(wa[2], wa[3]);
                u64t w45 = pack2(wa[4], wa[5]), w67 = pack2(wa[6], wa[7]);
                #pragma unroll
                for (int pp = 0; pp < 14; pp++) {
                    ulonglong2 v0 = *(const ulonglong2*)&coreb[(pbase + pp) * HP + k];
                    ulonglong2 v1 = *(const ulonglong2*)&coreb[(pbase + pp) * HP + k + 4];
                    fma2(acc[pp], v0.x, w01); fma2(acc[pp], v0.y, w23);
                    fma2(acc[pp], v1.x, w45); fma2(acc[pp], v1.y, w67);
                }
                #pragma unroll
                for (int j = 0; j < 8; j++) wa[j] = wb[j];
            }
            {
                u64t w01 = pack2(wa[0], wa[1]), w23 = pack2(wa[2], wa[3]);
                u64t w45 = pack2(wa[4], wa[5]), w67 = pack2(wa[6], wa[7]);
                #pragma unroll
                for (int pp = 0; pp < 14; pp++) {
                    ulonglong2 v0 = *(const ulonglong2*)&coreb[(pbase + pp) * HP + 240];
                    ulonglong2 v1 = *(const ulonglong2*)&coreb[(pbase + pp) * HP + 244];
                    fma2(acc[pp], v0.x, w01); fma2(acc[pp], v0.y, w23);
                    fma2(acc[pp], v1.x, w45); fma2(acc[pp], v1.y, w67);
                }
            }
            {
                u64t wt = pack2(Wc[248 * HA_], Wc[249 * HA_]);
                #pragma unroll
                for (int pp = 0; pp < 14; pp++) {
                    u64t v = *(const u64t*)&coreb[(pbase + pp) * HP + 248];
                    fma2(acc[pp], v, wt);
                }
            }
            float b1 = att_b1[ac];
            #pragma unroll
            for (int pp = 0; pp < 14; pp++)
                attb[(pbase + pp) * HA_ + ac] = tanhf(sum2(acc[pp]) + b1);
        }
    }
    __syncthreads();

    // ---- ctx LN stats + att LN + att2 + sigmoid (warp per pair) ----
    for (int p = warp; p < NP; p += 16) {
        {
            float s = 0.f, s2 = 0.f;
            for (int k = lane; k < H; k += 32) {
                float v = ctxb[p * HP + k];
                s += v; s2 += v * v;
            }
            #pragma unroll
            for (int off = 16; off; off >>= 1) {
                s  += __shfl_xor_sync(0xffffffffu, s,  off);
                s2 += __shfl_xor_sync(0xffffffffu, s2, off);
            }
            if (lane == 0) {
                float mu = s * (1.f / H);
                stC[2 * p]     = mu;
                stC[2 * p + 1] = rsqrtf(s2 * (1.f / H) - mu * mu + EPS_);
            }
        }
        {
            float s = 0.f, s2 = 0.f;
            for (int k = lane; k < HA_; k += 32) {
                float v = attb[p * HA_ + k];
                s += v; s2 += v * v;
            }
            #pragma unroll
            for (int off = 16; off; off >>= 1) {
                s  += __shfl_xor_sync(0xffffffffu, s,  off);
                s2 += __shfl_xor_sync(0xffffffffu, s2, off);
            }
            float mu = s * (1.f / HA_);
            float rs = rsqrtf(s2 * (1.f / HA_) - mu * mu + EPS_);
            float s3 = 0.f;
            for (int k = lane; k < HA_; k += 32) {
                float v = (attb[p * HA_ + k] - mu) * rs * att_g[k] + att_bt[k];
                s3 += v * att_W2[k];
            }
            #pragma unroll
            for (int off = 16; off; off >>= 1)
                s3 += __shfl_xor_sync(0xffffffffu, s3, off);
            if (lane == 0)
                attv[p] = 1.f / (1.f + expf(-(s3 + att_b2[0])));
        }
    }
    __syncthreads();

    // ---- effect accumulation ----
    if (t < H) {
        float gg = ctx_g[t], bb = ctx_bt[t];
        float eff[KK];
        #pragma unroll
        for (int e = 0; e < KK; e++) eff[e] = 0.f;
        #pragma unroll
        for (int p = 0; p < NP; p++) {
            const int i = p / 7;
            float v = ctxb[p * HP + t];
            v = (v - stC[2 * p]) * stC[2 * p + 1] * gg + bb;
            eff[i] += v * attv[p];
        }
        #pragma unroll
        for (int e = 0; e < KK; e++)
            g_eff[((size_t)grp * KK + e) * H + t] = eff[e];
    }
}

// ---------------------------------------------------------------------------
// Kernel 3: new_state = [s1, effect, x] @ out_W + out_b ; 32 rows / block
// ---------------------------------------------------------------------------
#define OR_ 32
__global__ __launch_bounds__(256, 1) void out_kernel(
    const float* __restrict__ x, const float* __restrict__ W,
    const float* __restrict__ b, float* __restrict__ out)
{
    extern __shared__ float tot[];   // OR_ * CIN floats
    const int t = threadIdx.x;
    const size_t base = (size_t)blockIdx.x * OR_;

    for (int i = t; i < OR_ * CIN; i += 256) {
        int r = i / CIN, k = i % CIN;
        size_t row = base + r;
        float v;
        if (k < H)           v = g_s1[row * H + k];
        else if (k < 2 * H)  v = g_eff[row * H + (k - H)];
        else                 v = x[row * MM + (k - 2 * H)];
        tot[r * CIN + k] = v;
    }
    __syncthreads();

    if (t >= H) return;
    const float* Wc = W + t;
    u64t acc[OR_];
    #pragma unroll
    for (int e = 0; e < OR_; e++) acc[e] = 0ull;

    float wa[8];
    #pragma unroll
    for (int j = 0; j < 8; j++) wa[j] = Wc[j * H];
    #pragma unroll 1
    for (int k = 0; k < 1064; k += 8) {     // chunks 0..1063, prefetch ≤1071
        float wb[8];
        #pragma unroll
        for (int j = 0; j < 8; j++) wb[j] = Wc[(k + 8 + j) * H];
        u64t w01 = pack2(wa[0], wa[1]), w23 = pack2(wa[2], wa[3]);
        u64t w45 = pack2(wa[4], wa[5]), w67 = pack2(wa[6], wa[7]);
        #pragma unroll
        for (int e = 0; e < OR_; e++) {
            ulonglong2 v0 = *(const ulonglong2*)&tot[e * CIN + k];
            ulonglong2 v1 = *(const ulonglong2*)&tot[e * CIN + k + 4];
            fma2(acc[e], v0.x, w01); fma2(acc[e], v0.y, w23);
            fma2(acc[e], v1.x, w45); fma2(acc[e], v1.y, w67);
        }
        #pragma unroll
        for (int j = 0; j < 8; j++) wa[j] = wb[j];
    }
    {   // k = 1064..1071 in wa
        u64t w01 = pack2(wa[0], wa[1]), w23 = pack2(wa[2], wa[3]);
        u64t w45 = pack2(wa[4], wa[5]), w67 = pack2(wa[6], wa[7]);
        #pragma unroll
        for (int e = 0; e < OR_; e++) {
            ulonglong2 v0 = *(const ulonglong2*)&tot[e * CIN + 1064];
            ulonglong2 v1 = *(const ulonglong2*)&tot[e * CIN + 1068];
            fma2(acc[e], v0.x, w01); fma2(acc[e], v0.y, w23);
            fma2(acc[e], v1.x, w45); fma2(acc[e], v1.y, w67);
        }
    }
    {   // tail k = 1072..1075
        u64t w01 = pack2(Wc[1072 * H], Wc[1073 * H]);
        u64t w23 = pack2(Wc[1074 * H], Wc[1075 * H]);
        #pragma unroll
        for (int e = 0; e < OR_; e++) {
            ulonglong2 v = *(const ulonglong2*)&tot[e * CIN + 1072];
            fma2(acc[e], v.x, w01); fma2(acc[e], v.y, w23);
        }
    }
    float bb = b[t];
    #pragma unroll
    for (int e = 0; e < OR_; e++)
        out[(base + e) * H + t] = sum2(acc[e]) + bb;
}

// ---------------------------------------------------------------------------
extern "C" void kernel_launch(void* const* d_in, const int* in_sizes, int n_in,
                              void* d_out, int out_size)
{
    const float* x       = (const float*)d_in[0];
    const float* state   = (const float*)d_in[1];
    const float* enc_W   = (const float*)d_in[2];
    const float* enc_b   = (const float*)d_in[3];
    const float* enc_g   = (const float*)d_in[4];
    const float* enc_bt  = (const float*)d_in[5];
    const float* core_W  = (const float*)d_in[6];
    const float* core_b  = (const float*)d_in[7];
    const float* core_g  = (const float*)d_in[8];
    const float* core_bt = (const float*)d_in[9];
    const float* ctx_W   = (const float*)d_in[10];
    const float* ctx_b   = (const float*)d_in[11];
    const float* ctx_g   = (const float*)d_in[12];
    const float* ctx_bt  = (const float*)d_in[13];
    const float* att_W1  = (const float*)d_in[14];
    const float* att_b1  = (const float*)d_in[15];
    const float* att_g   = (const float*)d_in[16];
    const float* att_bt  = (const float*)d_in[17];
    const float* att_W2  = (const float*)d_in[18];
    const float* att_b2  = (const float*)d_in[19];
    const float* out_W   = (const float*)d_in[20];
    const float* out_b   = (const float*)d_in[21];
    float* out = (float*)d_out;

    static int configured = 0;
    const int pair_smB = (3 * KK * HP + 2 * NP * HP + NP * HA_ + NP + 4 * NP) * (int)sizeof(float);
    const int out_smB  = OR_ * CIN * (int)sizeof(float);
    if (!configured) {
        cudaFuncSetAttribute(pair_kernel, cudaFuncAttributeMaxDynamicSharedMemorySize, pair_smB);
        cudaFuncSetAttribute(out_kernel,  cudaFuncAttributeMaxDynamicSharedMemorySize, out_smB);
        configured = 1;
    }

    enc_kernel<<<BK / ER, 256>>>(state, enc_W, enc_b, enc_g, enc_bt);
    pair_kernel<<<NB, 512, pair_smB>>>(core_W, core_b, core_g, core_bt,
                                       ctx_W, ctx_b, ctx_g, ctx_bt,
                                       att_W1, att_b1, att_g, att_bt,
                                       att_W2, att_b2);
    out_kernel<<<BK / OR_, 256, out_smB>>>(x, out_W, out_b, out);
}

// round 9
// speedup vs baseline: 1.2799x; 1.1744x over previous
#include <cuda_runtime.h>
#include <math.h>

#define KK   8
#define H    250
#define HP   252          // padded row stride (16B-aligned)
#define NP   56           // K*(K-1) pairs per group
#define HA_  100
#define MM   576
#define NB   2048         // batch groups
#define BK   (NB*KK)
#define CIN  1076         // 250 + 250 + 576
#define EPS_ 1e-5f

typedef unsigned long long u64t;

// f32x2 packed-FMA helpers (FFMA2 — PTX-only on sm_103a)
__device__ __forceinline__ u64t pack2(float lo, float hi) {
    u64t r;
    asm("mov.b64 %0, {%1, %2};" : "=l"(r) : "f"(lo), "f"(hi));
    return r;
}
__device__ __forceinline__ void fma2(u64t& d, u64t a, u64t b) {
    asm("fma.rn.f32x2 %0, %1, %2, %0;" : "+l"(d) : "l"(a), "l"(b));
}
__device__ __forceinline__ float sum2(u64t v) {
    float lo, hi;
    asm("mov.b64 {%0, %1}, %2;" : "=f"(lo), "=f"(hi) : "l"(v));
    return lo + hi;
}

// scratch (allocation-free rule: device globals)
__device__ float g_s1[(size_t)BK * H];
__device__ float g_eff[(size_t)BK * H];

// ---------------------------------------------------------------------------
// Kernel 1: s1 = LN(relu(state @ enc_W + enc_b)); 16 rows / block.
// 2 row-halves x 128 threads; each thread: 8 rows x 2 cols (c, c+128).
// ---------------------------------------------------------------------------
#define ER 16
__global__ __launch_bounds__(256, 2) void enc_kernel(
    const float* __restrict__ state, const float* __restrict__ W,
    const float* __restrict__ b, const float* __restrict__ g,
    const float* __restrict__ bt)
{
    __shared__ float sst[ER * HP];
    __shared__ float st[ER * 2];

    const int t = threadIdx.x;
    const size_t base = (size_t)blockIdx.x * ER;
    const float* srow = state + base * H;

    for (int i = t; i < ER * H; i += 256) {
        int r = i / H, c = i % H;
        sst[r * HP + c] = srow[i];
    }
    __syncthreads();

    const int h = t >> 7, u = t & 127;
    const int c0 = u, c1 = u + 128;
    const int c1ok = (c1 < H);
    const int c1v = c1ok ? c1 : 0;

    float relu0[8], relu1[8];
    {
        const float* W0 = W + c0;
        const float* W1 = W + c1v;
        const float* sr = sst + h * 8 * HP;
        u64t a0[8], a1[8];
        #pragma unroll
        for (int e = 0; e < 8; e++) { a0[e] = 0ull; a1[e] = 0ull; }

        float wa0[8], wa1[8];
        #pragma unroll
        for (int j = 0; j < 8; j++) { wa0[j] = W0[j * H]; wa1[j] = W1[j * H]; }
        #pragma unroll 1
        for (int k = 0; k < 240; k += 8) {
            float wb0[8], wb1[8];
            #pragma unroll
            for (int j = 0; j < 8; j++) {
                wb0[j] = W0[(k + 8 + j) * H];
                wb1[j] = W1[(k + 8 + j) * H];
            }
            u64t p00 = pack2(wa0[0], wa0[1]), p01 = pack2(wa0[2], wa0[3]);
            u64t p02 = pack2(wa0[4], wa0[5]), p03 = pack2(wa0[6], wa0[7]);
            u64t p10 = pack2(wa1[0], wa1[1]), p11 = pack2(wa1[2], wa1[3]);
            u64t p12 = pack2(wa1[4], wa1[5]), p13 = pack2(wa1[6], wa1[7]);
            #pragma unroll
            for (int e = 0; e < 8; e++) {
                ulonglong2 v0 = *(const ulonglong2*)&sr[e * HP + k];
                ulonglong2 v1 = *(const ulonglong2*)&sr[e * HP + k + 4];
                fma2(a0[e], v0.x, p00); fma2(a0[e], v0.y, p01);
                fma2(a0[e], v1.x, p02); fma2(a0[e], v1.y, p03);
                fma2(a1[e], v0.x, p10); fma2(a1[e], v0.y, p11);
                fma2(a1[e], v1.x, p12); fma2(a1[e], v1.y, p13);
            }
            #pragma unroll
            for (int j = 0; j < 8; j++) { wa0[j] = wb0[j]; wa1[j] = wb1[j]; }
        }
        {   // chunk k = 240..247 from wa
            u64t p00 = pack2(wa0[0], wa0[1]), p01 = pack2(wa0[2], wa0[3]);
            u64t p02 = pack2(wa0[4], wa0[5]), p03 = pack2(wa0[6], wa0[7]);
            u64t p10 = pack2(wa1[0], wa1[1]), p11 = pack2(wa1[2], wa1[3]);
            u64t p12 = pack2(wa1[4], wa1[5]), p13 = pack2(wa1[6], wa1[7]);
            #pragma unroll
            for (int e = 0; e < 8; e++) {
                ulonglong2 v0 = *(const ulonglong2*)&sr[e * HP + 240];
                ulonglong2 v1 = *(const ulonglong2*)&sr[e * HP + 244];
                fma2(a0[e], v0.x, p00); fma2(a0[e], v0.y, p01);
                fma2(a0[e], v1.x, p02); fma2(a0[e], v1.y, p03);
                fma2(a1[e], v0.x, p10); fma2(a1[e], v0.y, p11);
                fma2(a1[e], v1.x, p12); fma2(a1[e], v1.y, p13);
            }
        }
        {   // tail k = 248,249
            u64t wt0 = pack2(W0[248 * H], W0[249 * H]);
            u64t wt1 = pack2(W1[248 * H], W1[249 * H]);
            #pragma unroll
            for (int e = 0; e < 8; e++) {
                u64t v = *(const u64t*)&sr[e * HP + 248];
                fma2(a0[e], v, wt0);
                fma2(a1[e], v, wt1);
            }
        }
        float b0 = b[c0], b1 = b[c1v];
        #pragma unroll
        for (int e = 0; e < 8; e++) {
            relu0[e] = fmaxf(sum2(a0[e]) + b0, 0.f);
            relu1[e] = fmaxf(sum2(a1[e]) + b1, 0.f);
        }
    }
    __syncthreads();
    // write relu into sst (rows of own half only)
    #pragma unroll
    for (int e = 0; e < 8; e++) {
        sst[(8 * h + e) * HP + c0] = relu0[e];
        if (c1ok) sst[(8 * h + e) * HP + c1] = relu1[e];
    }
    __syncthreads();

    const int warp = t >> 5, lane = t & 31;
    for (int r = warp; r < ER; r += 8) {
        float s = 0.f, s2 = 0.f;
        for (int k = lane; k < H; k += 32) {
            float v = sst[r * HP + k];
            s += v; s2 += v * v;
        }
        #pragma unroll
        for (int off = 16; off; off >>= 1) {
            s  += __shfl_xor_sync(0xffffffffu, s,  off);
            s2 += __shfl_xor_sync(0xffffffffu, s2, off);
        }
        if (lane == 0) {
            float mu = s * (1.f / H);
            st[r * 2]     = mu;
            st[r * 2 + 1] = rsqrtf(s2 * (1.f / H) - mu * mu + EPS_);
        }
    }
    __syncthreads();

    {
        float g0 = g[c0], bb0 = bt[c0];
        float g1 = g[c1v], bb1 = bt[c1v];
        #pragma unroll
        for (int e = 0; e < 8; e++) {
            int r = 8 * h + e;
            g_s1[(base + r) * H + c0] = (relu0[e] - st[r * 2]) * st[r * 2 + 1] * g0 + bb0;
            if (c1ok)
                g_s1[(base + r) * H + c1] = (relu1[e] - st[r * 2]) * st[r * 2 + 1] * g1 + bb1;
        }
    }
}

// ---------------------------------------------------------------------------
// Kernel 2: fused per-group pair pipeline, 512 threads.
//   core: 4 groups (focal/other x k-half), all 512 threads busy, 2 cols each.
//   ctx:  4 quadrants x 14 pairs x 2 cols.  att1: 8 groups x 7 pairs x 2 cols.
// ---------------------------------------------------------------------------
__global__ __launch_bounds__(512, 1) void pair_kernel(
    const float* __restrict__ core_W, const float* __restrict__ core_b,
    const float* __restrict__ core_g, const float* __restrict__ core_bt,
    const float* __restrict__ ctx_W,  const float* __restrict__ ctx_b,
    const float* __restrict__ ctx_g,  const float* __restrict__ ctx_bt,
    const float* __restrict__ att_W1, const float* __restrict__ att_b1,
    const float* __restrict__ att_g,  const float* __restrict__ att_bt,
    const float* __restrict__ att_W2, const float* __restrict__ att_b2)
{
    extern __shared__ float sm[];
    float* s1s   = sm;                    // 8  * HP
    float* fbufA = s1s   + KK * HP;       // 8  * HP (focal, k 0..127)
    float* fbufB = fbufA + KK * HP;       // 8  * HP (focal, k 128..249)
    float* obufA = fbufB + KK * HP;       // 8  * HP (other, k 0..127)
    float* obufB = obufA + KK * HP;       // 8  * HP (other, k 128..249)
    float* coreb = obufB + KK * HP;       // 56 * HP
    float* ctxb  = coreb + NP * HP;       // 56 * HP
    float* attb  = ctxb  + NP * HP;       // 56 * HA_
    float* attv  = attb  + NP * HA_;      // 56
    float* stA   = attv  + NP;            // 56*2
    float* stC   = stA   + NP * 2;        // 56*2

    const int t = threadIdx.x;
    const int grp = blockIdx.x;
    const int warp = t >> 5, lane = t & 31;

    const int qg = t >> 7, u = t & 127;       // quadrant (0..3), lane-in-quadrant
    const int c0 = u, c1 = u + 128;
    const int c1ok = (c1 < H);
    const int c1v = c1ok ? c1 : 0;

    for (int i = t; i < KK * H; i += 512) {
        int r = i / H, c = i % H;
        s1s[r * HP + c] = g_s1[((size_t)grp * KK + r) * H + c];
    }
    __syncthreads();

    // ---- core GEMM: quadrant = (k-half, W-half); 2 cols per thread ----
    {
        const int wh = qg & 1;       // 0: focal W rows, 1: other W rows
        const int kh = qg >> 1;      // 0: k 0..127,  1: k 128..249
        const float* W0 = core_W + wh * 250 * H + c0;
        const float* W1 = core_W + wh * 250 * H + c1v;
        u64t a0[8], a1[8];
        #pragma unroll
        for (int e = 0; e < 8; e++) { a0[e] = 0ull; a1[e] = 0ull; }

        const int kstart = kh * 128;
        const int klast  = kh ? 240 : 120;
        float wa0[8], wa1[8];
        #pragma unroll
        for (int j = 0; j < 8; j++) {
            wa0[j] = W0[(kstart + j) * H];
            wa1[j] = W1[(kstart + j) * H];
        }
        #pragma unroll 1
        for (int k = kstart; k < klast; k += 8) {
            float wb0[8], wb1[8];
            #pragma unroll
            for (int j = 0; j < 8; j++) {
                wb0[j] = W0[(k + 8 + j) * H];
                wb1[j] = W1[(k + 8 + j) * H];
            }
            u64t p00 = pack2(wa0[0], wa0[1]), p01 = pack2(wa0[2], wa0[3]);
            u64t p02 = pack2(wa0[4], wa0[5]), p03 = pack2(wa0[6], wa0[7]);
            u64t p10 = pack2(wa1[0], wa1[1]), p11 = pack2(wa1[2], wa1[3]);
            u64t p12 = pack2(wa1[4], wa1[5]), p13 = pack2(wa1[6], wa1[7]);
            #pragma unroll
            for (int e = 0; e < 8; e++) {
                ulonglong2 v0 = *(const ulonglong2*)&s1s[e * HP + k];
                ulonglong2 v1 = *(const ulonglong2*)&s1s[e * HP + k + 4];
                fma2(a0[e], v0.x, p00); fma2(a0[e], v0.y, p01);
                fma2(a0[e], v1.x, p02); fma2(a0[e], v1.y, p03);
                fma2(a1[e], v0.x, p10); fma2(a1[e], v0.y, p11);
                fma2(a1[e], v1.x, p12); fma2(a1[e], v1.y, p13);
            }
            #pragma unroll
            for (int j = 0; j < 8; j++) { wa0[j] = wb0[j]; wa1[j] = wb1[j]; }
        }
        {   // last full chunk from wa
            u64t p00 = pack2(wa0[0], wa0[1]), p01 = pack2(wa0[2], wa0[3]);
            u64t p02 = pack2(wa0[4], wa0[5]), p03 = pack2(wa0[6], wa0[7]);
            u64t p10 = pack2(wa1[0], wa1[1]), p11 = pack2(wa1[2], wa1[3]);
            u64t p12 = pack2(wa1[4], wa1[5]), p13 = pack2(wa1[6], wa1[7]);
            #pragma unroll
            for (int e = 0; e < 8; e++) {
                ulonglong2 v0 = *(const ulonglong2*)&s1s[e * HP + klast];
                ulonglong2 v1 = *(const ulonglong2*)&s1s[e * HP + klast + 4];
                fma2(a0[e], v0.x, p00); fma2(a0[e], v0.y, p01);
                fma2(a0[e], v1.x, p02); fma2(a0[e], v1.y, p03);
                fma2(a1[e], v0.x, p10); fma2(a1[e], v0.y, p11);
                fma2(a1[e], v1.x, p12); fma2(a1[e], v1.y, p13);
            }
        }
        if (kh) {   // tail k = 248,249
            u64t wt0 = pack2(W0[248 * H], W0[249 * H]);
            u64t wt1 = pack2(W1[248 * H], W1[249 * H]);
            #pragma unroll
            for (int e = 0; e < 8; e++) {
                u64t v = *(const u64t*)&s1s[e * HP + 248];
                fma2(a0[e], v, wt0);
                fma2(a1[e], v, wt1);
            }
        }
        float* fd = kh ? (wh ? obufB : fbufB) : (wh ? obufA : fbufA);
        #pragma unroll
        for (int e = 0; e < 8; e++) {
            fd[e * HP + c0] = sum2(a0[e]);
            if (c1ok) fd[e * HP + c1] = sum2(a1[e]);
        }
    }
    __syncthreads();

    // ---- assemble coreb[p] = relu(focal + other + bias) ----
    for (int i = t; i < NP * H; i += 512) {
        int p = i / H, c = i % H;
        int fi = p / 7, jj = p % 7;
        int o = jj + (jj >= fi);
        coreb[p * HP + c] = fmaxf(fbufA[fi * HP + c] + fbufB[fi * HP + c]
                                + obufA[o * HP + c] + obufB[o * HP + c]
                                + core_b[c], 0.f);
    }
    __syncthreads();

    // ---- core LN stats (warp per pair, 16 warps) ----
    for (int p = warp; p < NP; p += 16) {
        float s = 0.f, s2 = 0.f;
        for (int k = lane; k < H; k += 32) {
            float v = coreb[p * HP + k];
            s += v; s2 += v * v;
        }
        #pragma unroll
        for (int off = 16; off; off >>= 1) {
            s  += __shfl_xor_sync(0xffffffffu, s,  off);
            s2 += __shfl_xor_sync(0xffffffffu, s2, off);
        }
        if (lane == 0) {
            float mu = s * (1.f / H);
            stA[2 * p]     = mu;
            stA[2 * p + 1] = rsqrtf(s2 * (1.f / H) - mu * mu + EPS_);
        }
    }
    __syncthreads();

    // ---- normalize coreb in place ----
    for (int i = t; i < NP * H; i += 512) {
        int p = i / H, c = i % H;
        float v = coreb[p * HP + c];
        coreb[p * HP + c] = (v - stA[2 * p]) * stA[2 * p + 1] * core_g[c] + core_bt[c];
    }
    __syncthreads();

    // ---- ctx GEMM: 4 quadrants x 14 pairs x 2 cols (4-k chunks) ----
    {
        const int pbase = qg * 14;
        const float* W0 = ctx_W + c0;
        const float* W1 = ctx_W + c1v;
        u64t a0[14], a1[14];
        #pragma unroll
        for (int pp = 0; pp < 14; pp++) { a0[pp] = 0ull; a1[pp] = 0ull; }

        float wa0[4], wa1[4];
        #pragma unroll
        for (int j = 0; j < 4; j++) { wa0[j] = W0[j * H]; wa1[j] = W1[j * H]; }
        #pragma unroll 1
        for (int k = 0; k < 244; k += 4) {
            float wb0[4], wb1[4];
            #pragma unroll
            for (int j = 0; j < 4; j++) {
                wb0[j] = W0[(k + 4 + j) * H];
                wb1[j] = W1[(k + 4 + j) * H];
            }
            u64t p00 = pack2(wa0[0], wa0[1]), p01 = pack2(wa0[2], wa0[3]);
            u64t p10 = pack2(wa1[0], wa1[1]), p11 = pack2(wa1[2], wa1[3]);
            #pragma unroll
            for (int pp = 0; pp < 14; pp++) {
                ulonglong2 v = *(const ulonglong2*)&coreb[(pbase + pp) * HP + k];
                fma2(a0[pp], v.x, p00); fma2(a0[pp], v.y, p01);
                fma2(a1[pp], v.x, p10); fma2(a1[pp], v.y, p11);
            }
            #pragma unroll
            for (int j = 0; j < 4; j++) { wa0[j] = wb0[j]; wa1[j] = wb1[j]; }
        }
        {   // chunk k = 244..247 from wa
            u64t p00 = pack2(wa0[0], wa0[1]), p01 = pack2(wa0[2], wa0[3]);
            u64t p10 = pack2(wa1[0], wa1[1]), p11 = pack2(wa1[2], wa1[3]);
            #pragma unroll
            for (int pp = 0; pp < 14; pp++) {
                ulonglong2 v = *(const ulonglong2*)&coreb[(pbase + pp) * HP + 244];
                fma2(a0[pp], v.x, p00); fma2(a0[pp], v.y, p01);
                fma2(a1[pp], v.x, p10); fma2(a1[pp], v.y, p11);
            }
        }
        {   // tail k = 248,249
            u64t wt0 = pack2(W0[248 * H], W0[249 * H]);
            u64t wt1 = pack2(W1[248 * H], W1[249 * H]);
            #pragma unroll
            for (int pp = 0; pp < 14; pp++) {
                u64t v = *(const u64t*)&coreb[(pbase + pp) * HP + 248];
                fma2(a0[pp], v, wt0);
                fma2(a1[pp], v, wt1);
            }
        }
        float b0 = ctx_b[c0], b1 = ctx_b[c1v];
        #pragma unroll
        for (int pp = 0; pp < 14; pp++) {
            ctxb[(pbase + pp) * HP + c0] = fmaxf(sum2(a0[pp]) + b0, 0.f);
            if (c1ok) ctxb[(pbase + pp) * HP + c1] = fmaxf(sum2(a1[pp]) + b1, 0.f);
        }
    }

    // ---- att1 GEMM: 8 groups x 7 pairs x 2 cols (reads coreb only) ----
    {
        const int g8 = t >> 6, u6 = t & 63;
        if (u6 < 50) {
            const int pbase = g8 * 7;
            const int ac0 = u6, ac1 = u6 + 50;
            const float* W0 = att_W1 + ac0;
            const float* W1 = att_W1 + ac1;
            u64t a0[7], a1[7];
            #pragma unroll
            for (int pp = 0; pp < 7; pp++) { a0[pp] = 0ull; a1[pp] = 0ull; }

            float wa0[8], wa1[8];
            #pragma unroll
            for (int j = 0; j < 8; j++) { wa0[j] = W0[j * HA_]; wa1[j] = W1[j * HA_]; }
            #pragma unroll 1
            for (int k = 0; k < 240; k += 8) {
                float wb0[8], wb1[8];
                #pragma unroll
                for (int j = 0; j < 8; j++) {
                    wb0[j] = W0[(k + 8 + j) * HA_];
                    wb1[j] = W1[(k + 8 + j) * HA_];
                }
                u64t p00 = pack2(wa0[0], wa0[1]), p01 = pack2(wa0[2], wa0[3]);
                u64t p02 = pack2(wa0[4], wa0[5]), p03 = pack2(wa0[6], wa0[7]);
                u64t p10 = pack2(wa1[0], wa1[1]), p11 = pack2(wa1[2], wa1[3]);
                u64t p12 = pack2(wa1[4], wa1[5]), p13 = pack2(wa1[6], wa1[7]);
                #pragma unroll
                for (int pp = 0; pp < 7; pp++) {
                    ulonglong2 v0 = *(const ulonglong2*)&coreb[(pbase + pp) * HP + k];
                    ulonglong2 v1 = *(const ulonglong2*)&coreb[(pbase + pp) * HP + k + 4];
                    fma2(a0[pp], v0.x, p00); fma2(a0[pp], v0.y, p01);
                    fma2(a0[pp], v1.x, p02); fma2(a0[pp], v1.y, p03);
                    fma2(a1[pp], v0.x, p10); fma2(a1[pp], v0.y, p11);
                    fma2(a1[pp], v1.x, p12); fma2(a1[pp], v1.y, p13);
                }
                #pragma unroll
                for (int j = 0; j < 8; j++) { wa0[j] = wb0[j]; wa1[j] = wb1[j]; }
            }
            {   // chunk 240..247 from wa
                u64t p00 = pack2(wa0[0], wa0[1]), p01 = pack2(wa0[2], wa0[3]);
                u64t p02 = pack2(wa0[4], wa0[5]), p03 = pack2(wa0[6], wa0[7]);
                u64t p10 = pack2(wa1[0], wa1[1]), p11 = pack2(wa1[2], wa1[3]);
                u64t p12 = pack2(wa1[4], wa1[5]), p13 = pack2(wa1[6], wa1[7]);
                #pragma unroll
                for (int pp = 0; pp < 7; pp++) {
                    ulonglong2 v0 = *(const ulonglong2*)&coreb[(pbase + pp) * HP + 240];
                    ulonglong2 v1 = *(const ulonglong2*)&coreb[(pbase + pp) * HP + 244];
                    fma2(a0[pp], v0.x, p00); fma2(a0[pp], v0.y, p01);
                    fma2(a0[pp], v1.x, p02); fma2(a0[pp], v1.y, p03);
                    fma2(a1[pp], v0.x, p10); fma2(a1[pp], v0.y, p11);
                    fma2(a1[pp], v1.x, p12); fma2(a1[pp], v1.y, p13);
                }
            }
            {   // tail 248,249
                u64t wt0 = pack2(W0[248 * HA_], W0[249 * HA_]);
                u64t wt1 = pack2(W1[248 * HA_], W1[249 * HA_]);
                #pragma unroll
                for (int pp = 0; pp < 7; pp++) {
                    u64t v = *(const u64t*)&coreb[(pbase + pp) * HP + 248];
                    fma2(a0[pp], v, wt0);
                    fma2(a1[pp], v, wt1);
                }
            }
            float b10 = att_b1[ac0], b11 = att_b1[ac1];
            #pragma unroll
            for (int pp = 0; pp < 7; pp++) {
                attb[(pbase + pp) * HA_ + ac0] = tanhf(sum2(a0[pp]) + b10);
                attb[(pbase + pp) * HA_ + ac1] = tanhf(sum2(a1[pp]) + b11);
            }
        }
    }
    __syncthreads();

    // ---- ctx LN stats + att LN + att2 + sigmoid (warp per pair) ----
    for (int p = warp; p < NP; p += 16) {
        {
            float s = 0.f, s2 = 0.f;
            for (int k = lane; k < H; k += 32) {
                float v = ctxb[p * HP + k];
                s += v; s2 += v * v;
            }
            #pragma unroll
            for (int off = 16; off; off >>= 1) {
                s  += __shfl_xor_sync(0xffffffffu, s,  off);
                s2 += __shfl_xor_sync(0xffffffffu, s2, off);
            }
            if (lane == 0) {
                float mu = s * (1.f / H);
                stC[2 * p]     = mu;
                stC[2 * p + 1] = rsqrtf(s2 * (1.f / H) - mu * mu + EPS_);
            }
        }
        {
            float s = 0.f, s2 = 0.f;
            for (int k = lane; k < HA_; k += 32) {
                float v = attb[p * HA_ + k];
                s += v; s2 += v * v;
            }
            #pragma unroll
            for (int off = 16; off; off >>= 1) {
                s  += __shfl_xor_sync(0xffffffffu, s,  off);
                s2 += __shfl_xor_sync(0xffffffffu, s2, off);
            }
            float mu = s * (1.f / HA_);
            float rs = rsqrtf(s2 * (1.f / HA_) - mu * mu + EPS_);
            float s3 = 0.f;
            for (int k = lane; k < HA_; k += 32) {
                float v = (attb[p * HA_ + k] - mu) * rs * att_g[k] + att_bt[k];
                s3 += v * att_W2[k];
            }
            #pragma unroll
            for (int off = 16; off; off >>= 1)
                s3 += __shfl_xor_sync(0xffffffffu, s3, off);
            if (lane == 0)
                attv[p] = 1.f / (1.f + expf(-(s3 + att_b2[0])));
        }
    }
    __syncthreads();

    // ---- effect accumulation ----
    if (t < H) {
        float gg = ctx_g[t], bb = ctx_bt[t];
        float eff[KK];
        #pragma unroll
        for (int e = 0; e < KK; e++) eff[e] = 0.f;
        #pragma unroll
        for (int p = 0; p < NP; p++) {
            const int i = p / 7;
            float v = ctxb[p * HP + t];
            v = (v - stC[2 * p]) * stC[2 * p + 1] * gg + bb;
            eff[i] += v * attv[p];
        }
        #pragma unroll
        for (int e = 0; e < KK; e++)
            g_eff[((size_t)grp * KK + e) * H + t] = eff[e];
    }
}

// ---------------------------------------------------------------------------
// Kernel 3: new_state = [s1, effect, x] @ out_W + out_b
// 32 rows / block, 512 threads: 4 row-groups x 128; 8 rows x 2 cols each.
// ---------------------------------------------------------------------------
#define OR_ 32
__global__ __launch_bounds__(512, 1) void out_kernel(
    const float* __restrict__ x, const float* __restrict__ W,
    const float* __restrict__ b, float* __restrict__ out)
{
    extern __shared__ float tot[];   // OR_ * CIN floats
    const int t = threadIdx.x;
    const size_t base = (size_t)blockIdx.x * OR_;

    for (int i = t; i < OR_ * CIN; i += 512) {
        int r = i / CIN, k = i % CIN;
        size_t row = base + r;
        float v;
        if (k < H)           v = g_s1[row * H + k];
        else if (k < 2 * H)  v = g_eff[row * H + (k - H)];
        else                 v = x[row * MM + (k - 2 * H)];
        tot[r * CIN + k] = v;
    }
    __syncthreads();

    const int rg = t >> 7, u = t & 127;
    const int c0 = u, c1 = u + 128;
    const int c1ok = (c1 < H);
    const int c1v = c1ok ? c1 : 0;
    const float* tr = tot + rg * 8 * CIN;
    const float* W0 = W + c0;
    const float* W1 = W + c1v;

    u64t a0[8], a1[8];
    #pragma unroll
    for (int e = 0; e < 8; e++) { a0[e] = 0ull; a1[e] = 0ull; }

    float wa0[8], wa1[8];
    #pragma unroll
    for (int j = 0; j < 8; j++) { wa0[j] = W0[j * H]; wa1[j] = W1[j * H]; }
    #pragma unroll 1
    for (int k = 0; k < 1064; k += 8) {
        float wb0[8], wb1[8];
        #pragma unroll
        for (int j = 0; j < 8; j++) {
            wb0[j] = W0[(k + 8 + j) * H];
            wb1[j] = W1[(k + 8 + j) * H];
        }
        u64t p00 = pack2(wa0[0], wa0[1]), p01 = pack2(wa0[2], wa0[3]);
        u64t p02 = pack2(wa0[4], wa0[5]), p03 = pack2(wa0[6], wa0[7]);
        u64t p10 = pack2(wa1[0], wa1[1]), p11 = pack2(wa1[2], wa1[3]);
        u64t p12 = pack2(wa1[4], wa1[5]), p13 = pack2(wa1[6], wa1[7]);
        #pragma unroll
        for (int e = 0; e < 8; e++) {
            ulonglong2 v0 = *(const ulonglong2*)&tr[e * CIN + k];
            ulonglong2 v1 = *(const ulonglong2*)&tr[e * CIN + k + 4];
            fma2(a0[e], v0.x, p00); fma2(a0[e], v0.y, p01);
            fma2(a0[e], v1.x, p02); fma2(a0[e], v1.y, p03);
            fma2(a1[e], v0.x, p10); fma2(a1[e], v0.y, p11);
            fma2(a1[e], v1.x, p12); fma2(a1[e], v1.y, p13);
        }
        #pragma unroll
        for (int j = 0; j < 8; j++) { wa0[j] = wb0[j]; wa1[j] = wb1[j]; }
    }
    {   // chunk k = 1064..1071 from wa
        u64t p00 = pack2(wa0[0], wa0[1]), p01 = pack2(wa0[2], wa0[3]);
        u64t p02 = pack2(wa0[4], wa0[5]), p03 = pack2(wa0[6], wa0[7]);
        u64t p10 = pack2(wa1[0], wa1[1]), p11 = pack2(wa1[2], wa1[3]);
        u64t p12 = pack2(wa1[4], wa1[5]), p13 = pack2(wa1[6], wa1[7]);
        #pragma unroll
        for (int e = 0; e < 8; e++) {
            ulonglong2 v0 = *(const ulonglong2*)&tr[e * CIN + 1064];
            ulonglong2 v1 = *(const ulonglong2*)&tr[e * CIN + 1068];
            fma2(a0[e], v0.x, p00); fma2(a0[e], v0.y, p01);
            fma2(a0[e], v1.x, p02); fma2(a0[e], v1.y, p03);
            fma2(a1[e], v0.x, p10); fma2(a1[e], v0.y, p11);
            fma2(a1[e], v1.x, p12); fma2(a1[e], v1.y, p13);
        }
    }
    {   // tail k = 1072..1075
        u64t w00 = pack2(W0[1072 * H], W0[1073 * H]);
        u64t w01 = pack2(W0[1074 * H], W0[1075 * H]);
        u64t w10 = pack2(W1[1072 * H], W1[1073 * H]);
        u64t w11 = pack2(W1[1074 * H], W1[1075 * H]);
        #pragma unroll
        for (int e = 0; e < 8; e++) {
            ulonglong2 v = *(const ulonglong2*)&tr[e * CIN + 1072];
            fma2(a0[e], v.x, w00); fma2(a0[e], v.y, w01);
            fma2(a1[e], v.x, w10); fma2(a1[e], v.y, w11);
        }
    }
    float b0 = b[c0], b1 = b[c1v];
    #pragma unroll
    for (int e = 0; e < 8; e++) {
        size_t row = base + rg * 8 + e;
        out[row * H + c0] = sum2(a0[e]) + b0;
        if (c1ok) out[row * H + c1] = sum2(a1[e]) + b1;
    }
}

// ---------------------------------------------------------------------------
extern "C" void kernel_launch(void* const* d_in, const int* in_sizes, int n_in,
                              void* d_out, int out_size)
{
    const float* x       = (const float*)d_in[0];
    const float* state   = (const float*)d_in[1];
    const float* enc_W   = (const float*)d_in[2];
    const float* enc_b   = (const float*)d_in[3];
    const float* enc_g   = (const float*)d_in[4];
    const float* enc_bt  = (const float*)d_in[5];
    const float* core_W  = (const float*)d_in[6];
    const float* core_b  = (const float*)d_in[7];
    const float* core_g  = (const float*)d_in[8];
    const float* core_bt = (const float*)d_in[9];
    const float* ctx_W   = (const float*)d_in[10];
    const float* ctx_b   = (const float*)d_in[11];
    const float* ctx_g   = (const float*)d_in[12];
    const float* ctx_bt  = (const float*)d_in[13];
    const float* att_W1  = (const float*)d_in[14];
    const float* att_b1  = (const float*)d_in[15];
    const float* att_g   = (const float*)d_in[16];
    const float* att_bt  = (const float*)d_in[17];
    const float* att_W2  = (const float*)d_in[18];
    const float* att_b2  = (const float*)d_in[19];
    const float* out_W   = (const float*)d_in[20];
    const float* out_b   = (const float*)d_in[21];
    float* out = (float*)d_out;

    static int configured = 0;
    const int pair_smB = (5 * KK * HP + 2 * NP * HP + NP * HA_ + NP + 4 * NP) * (int)sizeof(float);
    const int out_smB  = OR_ * CIN * (int)sizeof(float);
    if (!configured) {
        cudaFuncSetAttribute(pair_kernel, cudaFuncAttributeMaxDynamicSharedMemorySize, pair_smB);
        cudaFuncSetAttribute(out_kernel,  cudaFuncAttributeMaxDynamicSharedMemorySize, out_smB);
        configured = 1;
    }

    enc_kernel<<<BK / ER, 256>>>(state, enc_W, enc_b, enc_g, enc_bt);
    pair_kernel<<<NB, 512, pair_smB>>>(core_W, core_b, core_g, core_bt,
                                       ctx_W, ctx_b, ctx_g, ctx_bt,
                                       att_W1, att_b1, att_g, att_bt,
                                       att_W2, att_b2);
    out_kernel<<<BK / OR_, 512, out_smB>>>(x, out_W, out_b, out);
}